// round 2
// baseline (speedup 1.0000x reference)
#include <cuda_runtime.h>
#include <math.h>

#define MAXN 100000
#define MAXE 1600000

// ---------------- scratch (static device allocations only) ----------------
__device__ float g_deg_out[MAXN];              // deg_out -> rsqrt in place
__device__ float g_deg_in[MAXN];               // deg_in  -> rsqrt in place
__device__ float g_agg1[(size_t)MAXN * 128];
__device__ float g_h1  [(size_t)MAXN * 256];
__device__ float g_agg2[(size_t)MAXN * 256];
__device__ float g_z   [(size_t)MAXN * 64];
__device__ float g_agg3[(size_t)MAXN * 128];

// ---------------- helpers ----------------
__device__ __forceinline__ void red4(float* p, float4 v) {
    // 16B vector reduction: 4x fewer L2 atomic ops than scalar atomicAdd
    asm volatile("red.global.add.v4.f32 [%0], {%1, %2, %3, %4};"
                 :: "l"(p), "f"(v.x), "f"(v.y), "f"(v.z), "f"(v.w) : "memory");
}

// ---------------- zero scratch ----------------
__global__ void zero_kernel(int N) {
    int i = blockIdx.x * blockDim.x + threadIdx.x;   // float4 index
    float4 z4 = make_float4(0.f, 0.f, 0.f, 0.f);
    if (i < N * 32) reinterpret_cast<float4*>(g_agg1)[i] = z4;
    if (i < N * 64) reinterpret_cast<float4*>(g_agg2)[i] = z4;
    if (i < N * 32) reinterpret_cast<float4*>(g_agg3)[i] = z4;
    if (i < N) { g_deg_out[i] = 0.f; g_deg_in[i] = 0.f; }
}

// ---------------- degrees ----------------
__global__ void degree_kernel(const int* __restrict__ src, const int* __restrict__ dst, int E) {
    int i = blockIdx.x * blockDim.x + threadIdx.x;
    if (i >= E) return;
    atomicAdd(&g_deg_out[src[i]], 1.0f);
    atomicAdd(&g_deg_in [dst[i]], 1.0f);
}

__global__ void rsqrt_kernel(int N) {
    int i = blockIdx.x * blockDim.x + threadIdx.x;
    if (i >= N) return;
    g_deg_out[i] = rsqrtf(fmaxf(g_deg_out[i], 1.0f));
    g_deg_in [i] = rsqrtf(fmaxf(g_deg_in [i], 1.0f));
}

// ---------------- scatter (SpMM, atomic scatter-add) ----------------
// DIM=128: one warp per edge, 1 float4 per lane
__global__ void scatter_d128(const float* __restrict__ x,
                             const int* __restrict__ src, const int* __restrict__ dst,
                             float* __restrict__ agg, int E) {
    int t = blockIdx.x * blockDim.x + threadIdx.x;
    int e = t >> 5, lane = t & 31;
    if (e >= E) return;
    int s = __ldg(src + e), d = __ldg(dst + e);
    float w = __ldg(&g_deg_out[s]);
    float4 v = __ldg(reinterpret_cast<const float4*>(x) + (size_t)s * 32 + lane);
    v.x *= w; v.y *= w; v.z *= w; v.w *= w;
    red4(agg + (size_t)d * 128 + lane * 4, v);
}

// DIM=256: one warp per edge, 2 float4 per lane
__global__ void scatter_d256(const float* __restrict__ x,
                             const int* __restrict__ src, const int* __restrict__ dst,
                             float* __restrict__ agg, int E) {
    int t = blockIdx.x * blockDim.x + threadIdx.x;
    int e = t >> 5, lane = t & 31;
    if (e >= E) return;
    int s = __ldg(src + e), d = __ldg(dst + e);
    float w = __ldg(&g_deg_out[s]);
    const float4* xr = reinterpret_cast<const float4*>(x) + (size_t)s * 64;
    float4 v0 = __ldg(xr + lane);
    float4 v1 = __ldg(xr + 32 + lane);
    v0.x *= w; v0.y *= w; v0.z *= w; v0.w *= w;
    v1.x *= w; v1.y *= w; v1.z *= w; v1.w *= w;
    float* a = agg + (size_t)d * 256;
    red4(a + lane * 4, v0);
    red4(a + 128 + lane * 4, v1);
}

// DIM=64: half-warp per edge, 1 float4 per lane
__global__ void scatter_d64(const float* __restrict__ x,
                            const int* __restrict__ src, const int* __restrict__ dst,
                            float* __restrict__ agg, int E) {
    int t = blockIdx.x * blockDim.x + threadIdx.x;
    int e = t >> 4, lane = t & 15;
    if (e >= E) return;
    int s = __ldg(src + e), d = __ldg(dst + e);
    float w = __ldg(&g_deg_out[s]);
    float4 v = __ldg(reinterpret_cast<const float4*>(x) + (size_t)s * 16 + lane);
    v.x *= w; v.y *= w; v.z *= w; v.w *= w;
    red4(agg + (size_t)d * 64 + lane * 4, v);
}

// ---------------- GEMM 1: h1 = relu((agg1 * din) @ W1[128x256] + b1) ----------------
// block = 256 thr, 64 rows per block. W in smem (128KB), x tile in smem (32KB).
__global__ void gemm1_kernel(const float* __restrict__ W, const float* __restrict__ b, int N) {
    extern __shared__ float sm[];
    float* Ws = sm;               // 128*256
    float* xs = sm + 128 * 256;   // 64*128
    int tid = threadIdx.x;
    int row0 = blockIdx.x * 64;

    const float4* Wv = reinterpret_cast<const float4*>(W);
    float4* Wsv = reinterpret_cast<float4*>(Ws);
    #pragma unroll
    for (int i = tid; i < 128 * 256 / 4; i += 256) Wsv[i] = Wv[i];

    for (int i = tid; i < 64 * 32; i += 256) {     // float4 index into x tile
        int r = i >> 5, c = i & 31;
        int n = row0 + r;
        float4 v = make_float4(0.f, 0.f, 0.f, 0.f);
        if (n < N) {
            v = reinterpret_cast<const float4*>(g_agg1)[(size_t)n * 32 + c];
            float s = g_deg_in[n];
            v.x *= s; v.y *= s; v.z *= s; v.w *= s;
        }
        reinterpret_cast<float4*>(xs)[i] = v;
    }
    __syncthreads();

    int j = tid & 127;
    int g = tid >> 7;           // 0..1
    float bj0 = __ldg(b + j), bj1 = __ldg(b + 128 + j);

    for (int pass = 0; pass < 8; ++pass) {
        int rbase = pass * 8 + g * 4;
        float acc[4][2] = {};
        #pragma unroll 4
        for (int k = 0; k < 128; ++k) {
            float w0 = Ws[k * 256 + j];
            float w1 = Ws[k * 256 + 128 + j];
            #pragma unroll
            for (int r = 0; r < 4; ++r) {
                float xv = xs[(rbase + r) * 128 + k];
                acc[r][0] = fmaf(xv, w0, acc[r][0]);
                acc[r][1] = fmaf(xv, w1, acc[r][1]);
            }
        }
        #pragma unroll
        for (int r = 0; r < 4; ++r) {
            int n = row0 + rbase + r;
            if (n < N) {
                g_h1[(size_t)n * 256 + j]       = fmaxf(acc[r][0] + bj0, 0.f);
                g_h1[(size_t)n * 256 + 128 + j] = fmaxf(acc[r][1] + bj1, 0.f);
            }
        }
    }
}

// ---------------- GEMM 2 (fused): ml = (agg2 * din) @ W2[256x128] + b2
//   mean -> out_mean, log_var -> out_lv, z = eps*exp(0.5 lv)+mean -> g_z
__global__ void gemm2_kernel(const float* __restrict__ W, const float* __restrict__ b,
                             const float* __restrict__ eps,
                             float* __restrict__ out_mean, float* __restrict__ out_lv, int N) {
    extern __shared__ float sm[];
    float* Ws = sm;               // 256*128
    float* xs = sm + 256 * 128;   // 64*256
    int tid = threadIdx.x;
    int row0 = blockIdx.x * 64;

    const float4* Wv = reinterpret_cast<const float4*>(W);
    float4* Wsv = reinterpret_cast<float4*>(Ws);
    #pragma unroll
    for (int i = tid; i < 256 * 128 / 4; i += 256) Wsv[i] = Wv[i];

    for (int i = tid; i < 64 * 64; i += 256) {     // float4 index
        int r = i >> 6, c = i & 63;
        int n = row0 + r;
        float4 v = make_float4(0.f, 0.f, 0.f, 0.f);
        if (n < N) {
            v = reinterpret_cast<const float4*>(g_agg2)[(size_t)n * 64 + c];
            float s = g_deg_in[n];
            v.x *= s; v.y *= s; v.z *= s; v.w *= s;
        }
        reinterpret_cast<float4*>(xs)[i] = v;
    }
    __syncthreads();

    int j = tid & 63;
    int g = tid >> 6;           // 0..3
    float bm = __ldg(b + j), bl = __ldg(b + 64 + j);

    for (int pass = 0; pass < 4; ++pass) {
        int rbase = pass * 16 + g * 4;
        float acc[4][2] = {};
        #pragma unroll 4
        for (int k = 0; k < 256; ++k) {
            float wm = Ws[k * 128 + j];
            float wl = Ws[k * 128 + 64 + j];
            #pragma unroll
            for (int r = 0; r < 4; ++r) {
                float xv = xs[(rbase + r) * 256 + k];
                acc[r][0] = fmaf(xv, wm, acc[r][0]);
                acc[r][1] = fmaf(xv, wl, acc[r][1]);
            }
        }
        #pragma unroll
        for (int r = 0; r < 4; ++r) {
            int n = row0 + rbase + r;
            if (n < N) {
                float mean = acc[r][0] + bm;
                float lv   = acc[r][1] + bl;
                size_t o = (size_t)n * 64 + j;
                out_mean[o] = mean;
                out_lv[o]   = lv;
                g_z[o] = fmaf(__ldg(eps + o), expf(0.5f * lv), mean);
            }
        }
    }
}

// ---------------- GEMM 3: recon = (agg3 * din) @ W3[64x128] + b3 ----------------
__global__ void gemm3_kernel(const float* __restrict__ W, const float* __restrict__ b,
                             float* __restrict__ out, int N) {
    extern __shared__ float sm[];
    float* Ws = sm;               // 64*128
    float* xs = sm + 64 * 128;    // 64*64
    int tid = threadIdx.x;
    int row0 = blockIdx.x * 64;

    const float4* Wv = reinterpret_cast<const float4*>(W);
    float4* Wsv = reinterpret_cast<float4*>(Ws);
    #pragma unroll
    for (int i = tid; i < 64 * 128 / 4; i += 256) Wsv[i] = Wv[i];

    for (int i = tid; i < 64 * 16; i += 256) {     // float4 index
        int r = i >> 4, c = i & 15;
        int n = row0 + r;
        float4 v = make_float4(0.f, 0.f, 0.f, 0.f);
        if (n < N) {
            v = reinterpret_cast<const float4*>(g_agg3)[(size_t)n * 16 + c];
            float s = g_deg_in[n];
            v.x *= s; v.y *= s; v.z *= s; v.w *= s;
        }
        reinterpret_cast<float4*>(xs)[i] = v;
    }
    __syncthreads();

    int j = tid & 127;
    int g = tid >> 7;           // 0..1
    float bj = __ldg(b + j);

    for (int pass = 0; pass < 8; ++pass) {
        int rbase = pass * 8 + g * 4;
        float acc[4] = {};
        #pragma unroll
        for (int k = 0; k < 64; ++k) {
            float w0 = Ws[k * 128 + j];
            #pragma unroll
            for (int r = 0; r < 4; ++r)
                acc[r] = fmaf(xs[(rbase + r) * 64 + k], w0, acc[r]);
        }
        #pragma unroll
        for (int r = 0; r < 4; ++r) {
            int n = row0 + rbase + r;
            if (n < N) out[(size_t)n * 128 + j] = acc[r] + bj;
        }
    }
}

// ---------------- launch ----------------
extern "C" void kernel_launch(void* const* d_in, const int* in_sizes, int n_in,
                              void* d_out, int out_size) {
    const float* features = (const float*)d_in[0];
    const int*   src      = (const int*)  d_in[1];
    const int*   dst      = (const int*)  d_in[2];
    const float* eps      = (const float*)d_in[3];
    const float* W1       = (const float*)d_in[4];
    const float* b1       = (const float*)d_in[5];
    const float* W2       = (const float*)d_in[6];
    const float* b2       = (const float*)d_in[7];
    const float* W3       = (const float*)d_in[8];
    const float* b3       = (const float*)d_in[9];

    int N = in_sizes[0] / 128;
    int E = in_sizes[1];

    float* out   = (float*)d_out;
    float* recon = out;
    float* mean  = out + (size_t)N * 128;
    float* logv  = mean + (size_t)N * 64;

    // scratch pointers come from __device__ globals inside the kernels.
    const int SMEM_G1 = (128 * 256 + 64 * 128) * 4;  // 160KB
    const int SMEM_G2 = (256 * 128 + 64 * 256) * 4;  // 192KB
    const int SMEM_G3 = (64 * 128 + 64 * 64) * 4;    // 48KB
    cudaFuncSetAttribute(gemm1_kernel, cudaFuncAttributeMaxDynamicSharedMemorySize, SMEM_G1);
    cudaFuncSetAttribute(gemm2_kernel, cudaFuncAttributeMaxDynamicSharedMemorySize, SMEM_G2);
    cudaFuncSetAttribute(gemm3_kernel, cudaFuncAttributeMaxDynamicSharedMemorySize, SMEM_G3);

    int gemm_grid = (N + 63) / 64;

    // get raw device pointers for the scratch symbols used as kernel args
    // (kernels reference the __device__ globals directly; only scatter needs them passed)
    // We pass through small trampoline kernels instead: scatter takes agg pointer.
    // Obtain addresses via cudaGetSymbolAddress (host API, capture-safe).
    void *p_agg1, *p_agg2, *p_agg3;
    cudaGetSymbolAddress(&p_agg1, g_agg1);
    cudaGetSymbolAddress(&p_agg2, g_agg2);
    cudaGetSymbolAddress(&p_agg3, g_agg3);
    void *p_h1, *p_z;
    cudaGetSymbolAddress(&p_h1, g_h1);
    cudaGetSymbolAddress(&p_z, g_z);

    zero_kernel<<<(N * 64 + 255) / 256, 256>>>(N);
    degree_kernel<<<(E + 255) / 256, 256>>>(src, dst, E);
    rsqrt_kernel<<<(N + 255) / 256, 256>>>(N);

    // layer 1: scatter features (D=128) -> agg1, then GEMM+relu -> h1
    scatter_d128<<<(E + 7) / 8, 256>>>(features, src, dst, (float*)p_agg1, E);
    gemm1_kernel<<<gemm_grid, 256, SMEM_G1>>>(W1, b1, N);

    // layer 2: scatter h1 (D=256) -> agg2, then GEMM -> mean/logvar/z
    scatter_d256<<<(E + 7) / 8, 256>>>((const float*)p_h1, src, dst, (float*)p_agg2, E);
    gemm2_kernel<<<gemm_grid, 256, SMEM_G2>>>(W2, b2, eps, mean, logv, N);

    // layer 3: scatter z (D=64) -> agg3, then GEMM -> recon
    scatter_d64<<<(E + 15) / 16, 256>>>((const float*)p_z, src, dst, (float*)p_agg3, E);
    gemm3_kernel<<<gemm_grid, 256, SMEM_G3>>>(W3, b3, recon, N);
}

// round 4
// speedup vs baseline: 1.7130x; 1.7130x over previous
#include <cuda_runtime.h>
#include <math.h>

#define MAXN 100000
#define MAXE 1600000
#define SCAN_B 1024

// ---------------- scratch (static device globals only) ----------------
__device__ int   g_cnt_in [MAXN];
__device__ int   g_cnt_out[MAXN];
__device__ int   g_fill   [MAXN];
__device__ int   g_rowptr [MAXN + 1];
__device__ int   g_csr_src[MAXE];
__device__ int   g_blocksums[1024];
__device__ float g_dout[MAXN];            // rsqrt(out-degree)
__device__ float g_din [MAXN];            // rsqrt(in-degree)
__device__ float g_agg1[(size_t)MAXN * 128];   // din * segsum(feat*dout)
__device__ float g_h1  [(size_t)MAXN * 256];   // relu(agg1 @ W1 + b1)
__device__ float g_y2  [(size_t)MAXN * 128];   // (h1*dout) @ W2
__device__ float g_z   [(size_t)MAXN * 64];    // reparameterized latent
__device__ float g_agg3[(size_t)MAXN * 64];    // din * segsum(z*dout)

// ---------------- setup: zero counters ----------------
__global__ void zero_small(int N) {
    int i = blockIdx.x * blockDim.x + threadIdx.x;
    if (i < N) { g_cnt_in[i] = 0; g_cnt_out[i] = 0; g_fill[i] = 0; }
}

// ---------------- degrees (int histogram) ----------------
__global__ void hist_kernel(const int* __restrict__ src, const int* __restrict__ dst, int E) {
    int i = blockIdx.x * blockDim.x + threadIdx.x;
    if (i >= E) return;
    atomicAdd(&g_cnt_out[src[i]], 1);
    atomicAdd(&g_cnt_in [dst[i]], 1);
}

__global__ void rsqrt_kernel(int N) {
    int i = blockIdx.x * blockDim.x + threadIdx.x;
    if (i >= N) return;
    g_dout[i] = rsqrtf((float)max(g_cnt_out[i], 1));
    g_din [i] = rsqrtf((float)max(g_cnt_in [i], 1));
}

// ---------------- exclusive scan of cnt_in -> rowptr ----------------
__global__ void scan_part(int N) {
    __shared__ int sm[SCAN_B];
    int tid = threadIdx.x;
    int i = blockIdx.x * SCAN_B + tid;
    int v = (i < N) ? g_cnt_in[i] : 0;
    sm[tid] = v;
    __syncthreads();
    #pragma unroll
    for (int off = 1; off < SCAN_B; off <<= 1) {
        int t = (tid >= off) ? sm[tid - off] : 0;
        __syncthreads();
        sm[tid] += t;
        __syncthreads();
    }
    if (i < N) g_rowptr[i] = sm[tid] - v;       // partial exclusive
    if (tid == SCAN_B - 1) g_blocksums[blockIdx.x] = sm[tid];
}

__global__ void scan_tops(int nb) {
    if (threadIdx.x == 0) {
        int acc = 0;
        for (int b = 0; b < nb; ++b) { int t = g_blocksums[b]; g_blocksums[b] = acc; acc += t; }
    }
}

__global__ void scan_add(int N, int E) {
    int i = blockIdx.x * blockDim.x + threadIdx.x;
    if (i < N) g_rowptr[i] += g_blocksums[i / SCAN_B];
    if (i == 0) g_rowptr[N] = E;
}

// ---------------- CSR fill (src ids grouped by dst) ----------------
__global__ void fill_kernel(const int* __restrict__ src, const int* __restrict__ dst, int E) {
    int i = blockIdx.x * blockDim.x + threadIdx.x;
    if (i >= E) return;
    int d = dst[i];
    int pos = g_rowptr[d] + atomicAdd(&g_fill[d], 1);
    g_csr_src[pos] = src[i];
}

// ---------------- gather aggregations (atomic-free) ----------------
// layer1: agg1[d] = din[d] * sum_{s in N(d)} dout[s] * x[s]   (D=128, warp/node)
__global__ void gather_d128_l1(const float* __restrict__ x, int N) {
    int t = blockIdx.x * blockDim.x + threadIdx.x;
    int node = t >> 5, lane = t & 31;
    if (node >= N) return;
    int beg = g_rowptr[node], end = g_rowptr[node + 1];
    const float4* x4 = reinterpret_cast<const float4*>(x);
    float4 acc = make_float4(0.f, 0.f, 0.f, 0.f);
    #pragma unroll 4
    for (int k = beg; k < end; ++k) {
        int s = __ldg(g_csr_src + k);
        float w = __ldg(g_dout + s);
        float4 v = __ldg(x4 + (size_t)s * 32 + lane);
        acc.x = fmaf(w, v.x, acc.x);
        acc.y = fmaf(w, v.y, acc.y);
        acc.z = fmaf(w, v.z, acc.z);
        acc.w = fmaf(w, v.w, acc.w);
    }
    float di = g_din[node];
    acc.x *= di; acc.y *= di; acc.z *= di; acc.w *= di;
    reinterpret_cast<float4*>(g_agg1)[(size_t)node * 32 + lane] = acc;
}

// layer2 fused: ml[d] = din[d] * sum y2[s] + b2 ; split mean/logvar; z = eps*exp(.5lv)+mean
// y2 already contains the dout[src] scaling (folded into GEMM2 input).
__global__ void gather_d128_l2_vae(const float* __restrict__ b2, const float* __restrict__ eps,
                                   float* __restrict__ out_mean, float* __restrict__ out_lv, int N) {
    int t = blockIdx.x * blockDim.x + threadIdx.x;
    int node = t >> 5, lane = t & 31;
    if (node >= N) return;
    int beg = g_rowptr[node], end = g_rowptr[node + 1];
    const float4* y4 = reinterpret_cast<const float4*>(g_y2);
    float4 acc = make_float4(0.f, 0.f, 0.f, 0.f);
    #pragma unroll 4
    for (int k = beg; k < end; ++k) {
        int s = __ldg(g_csr_src + k);
        float4 v = __ldg(y4 + (size_t)s * 32 + lane);
        acc.x += v.x; acc.y += v.y; acc.z += v.z; acc.w += v.w;
    }
    float di = g_din[node];
    float4 bb = __ldg(reinterpret_cast<const float4*>(b2) + lane);
    acc.x = fmaf(acc.x, di, bb.x);
    acc.y = fmaf(acc.y, di, bb.y);
    acc.z = fmaf(acc.z, di, bb.z);
    acc.w = fmaf(acc.w, di, bb.w);
    // lanes 0..15 hold mean (cols 0..63), lanes 16..31 hold log_var (cols 64..127)
    float4 other;
    other.x = __shfl_xor_sync(0xffffffffu, acc.x, 16);
    other.y = __shfl_xor_sync(0xffffffffu, acc.y, 16);
    other.z = __shfl_xor_sync(0xffffffffu, acc.z, 16);
    other.w = __shfl_xor_sync(0xffffffffu, acc.w, 16);
    if (lane < 16) {
        size_t o = (size_t)node * 16 + lane;
        reinterpret_cast<float4*>(out_mean)[o] = acc;
        float4 e = __ldg(reinterpret_cast<const float4*>(eps) + o);
        float4 z;
        z.x = fmaf(e.x, expf(0.5f * other.x), acc.x);
        z.y = fmaf(e.y, expf(0.5f * other.y), acc.y);
        z.z = fmaf(e.z, expf(0.5f * other.z), acc.z);
        z.w = fmaf(e.w, expf(0.5f * other.w), acc.w);
        reinterpret_cast<float4*>(g_z)[o] = z;
    } else {
        reinterpret_cast<float4*>(out_lv)[(size_t)node * 16 + (lane - 16)] = acc;
    }
}

// layer3: agg3[d] = din[d] * sum dout[s]*z[s]   (D=64, 16 threads/node)
__global__ void gather_d64_l3(int N) {
    int t = blockIdx.x * blockDim.x + threadIdx.x;
    int node = t >> 4, lane = t & 15;
    if (node >= N) return;
    int beg = g_rowptr[node], end = g_rowptr[node + 1];
    const float4* z4 = reinterpret_cast<const float4*>(g_z);
    float4 acc = make_float4(0.f, 0.f, 0.f, 0.f);
    #pragma unroll 4
    for (int k = beg; k < end; ++k) {
        int s = __ldg(g_csr_src + k);
        float w = __ldg(g_dout + s);
        float4 v = __ldg(z4 + (size_t)s * 16 + lane);
        acc.x = fmaf(w, v.x, acc.x);
        acc.y = fmaf(w, v.y, acc.y);
        acc.z = fmaf(w, v.z, acc.z);
        acc.w = fmaf(w, v.w, acc.w);
    }
    float di = g_din[node];
    acc.x *= di; acc.y *= di; acc.z *= di; acc.w *= di;
    reinterpret_cast<float4*>(g_agg3)[(size_t)node * 16 + lane] = acc;
}

// ---------------- GEMM 1: h1 = relu(agg1 @ W1[128x256] + b1) ----------------
__global__ void gemm1_kernel(const float* __restrict__ W, const float* __restrict__ b, int N) {
    extern __shared__ float sm[];
    float* Ws = sm;               // 128*256
    float* xs = sm + 128 * 256;   // 64*128
    int tid = threadIdx.x;
    int row0 = blockIdx.x * 64;

    const float4* Wv = reinterpret_cast<const float4*>(W);
    float4* Wsv = reinterpret_cast<float4*>(Ws);
    #pragma unroll
    for (int i = tid; i < 128 * 256 / 4; i += 256) Wsv[i] = Wv[i];

    for (int i = tid; i < 64 * 32; i += 256) {
        int r = i >> 5, c = i & 31;
        int n = row0 + r;
        float4 v = make_float4(0.f, 0.f, 0.f, 0.f);
        if (n < N) v = reinterpret_cast<const float4*>(g_agg1)[(size_t)n * 32 + c];
        reinterpret_cast<float4*>(xs)[i] = v;
    }
    __syncthreads();

    int j = tid & 127;
    int g = tid >> 7;
    float bj0 = __ldg(b + j), bj1 = __ldg(b + 128 + j);

    for (int pass = 0; pass < 8; ++pass) {
        int rbase = pass * 8 + g * 4;
        float acc[4][2] = {};
        #pragma unroll 4
        for (int k = 0; k < 128; ++k) {
            float w0 = Ws[k * 256 + j];
            float w1 = Ws[k * 256 + 128 + j];
            #pragma unroll
            for (int r = 0; r < 4; ++r) {
                float xv = xs[(rbase + r) * 128 + k];
                acc[r][0] = fmaf(xv, w0, acc[r][0]);
                acc[r][1] = fmaf(xv, w1, acc[r][1]);
            }
        }
        #pragma unroll
        for (int r = 0; r < 4; ++r) {
            int n = row0 + rbase + r;
            if (n < N) {
                g_h1[(size_t)n * 256 + j]       = fmaxf(acc[r][0] + bj0, 0.f);
                g_h1[(size_t)n * 256 + 128 + j] = fmaxf(acc[r][1] + bj1, 0.f);
            }
        }
    }
}

// ---------------- GEMM 2 (reordered): y2 = (h1 * dout) @ W2[256x128] ----------------
__global__ void gemm2_kernel(const float* __restrict__ W, int N) {
    extern __shared__ float sm[];
    float* Ws = sm;               // 256*128
    float* xs = sm + 256 * 128;   // 64*256
    int tid = threadIdx.x;
    int row0 = blockIdx.x * 64;

    const float4* Wv = reinterpret_cast<const float4*>(W);
    float4* Wsv = reinterpret_cast<float4*>(Ws);
    #pragma unroll
    for (int i = tid; i < 256 * 128 / 4; i += 256) Wsv[i] = Wv[i];

    for (int i = tid; i < 64 * 64; i += 256) {
        int r = i >> 6, c = i & 63;
        int n = row0 + r;
        float4 v = make_float4(0.f, 0.f, 0.f, 0.f);
        if (n < N) {
            v = reinterpret_cast<const float4*>(g_h1)[(size_t)n * 64 + c];
            float s = g_dout[n];               // fold src-side degree scaling here
            v.x *= s; v.y *= s; v.z *= s; v.w *= s;
        }
        reinterpret_cast<float4*>(xs)[i] = v;
    }
    __syncthreads();

    int j = tid & 63;
    int g = tid >> 6;

    for (int pass = 0; pass < 4; ++pass) {
        int rbase = pass * 16 + g * 4;
        float acc[4][2] = {};
        #pragma unroll 4
        for (int k = 0; k < 256; ++k) {
            float wm = Ws[k * 128 + j];
            float wl = Ws[k * 128 + 64 + j];
            #pragma unroll
            for (int r = 0; r < 4; ++r) {
                float xv = xs[(rbase + r) * 256 + k];
                acc[r][0] = fmaf(xv, wm, acc[r][0]);
                acc[r][1] = fmaf(xv, wl, acc[r][1]);
            }
        }
        #pragma unroll
        for (int r = 0; r < 4; ++r) {
            int n = row0 + rbase + r;
            if (n < N) {
                g_y2[(size_t)n * 128 + j]      = acc[r][0];
                g_y2[(size_t)n * 128 + 64 + j] = acc[r][1];
            }
        }
    }
}

// ---------------- GEMM 3: recon = agg3 @ W3[64x128] + b3 ----------------
__global__ void gemm3_kernel(const float* __restrict__ W, const float* __restrict__ b,
                             float* __restrict__ out, int N) {
    extern __shared__ float sm[];
    float* Ws = sm;               // 64*128
    float* xs = sm + 64 * 128;    // 64*64
    int tid = threadIdx.x;
    int row0 = blockIdx.x * 64;

    const float4* Wv = reinterpret_cast<const float4*>(W);
    float4* Wsv = reinterpret_cast<float4*>(Ws);
    #pragma unroll
    for (int i = tid; i < 64 * 128 / 4; i += 256) Wsv[i] = Wv[i];

    for (int i = tid; i < 64 * 16; i += 256) {
        int r = i >> 4, c = i & 15;
        int n = row0 + r;
        float4 v = make_float4(0.f, 0.f, 0.f, 0.f);
        if (n < N) v = reinterpret_cast<const float4*>(g_agg3)[(size_t)n * 16 + c];
        reinterpret_cast<float4*>(xs)[i] = v;
    }
    __syncthreads();

    int j = tid & 127;
    int g = tid >> 7;
    float bj = __ldg(b + j);

    for (int pass = 0; pass < 8; ++pass) {
        int rbase = pass * 8 + g * 4;
        float acc[4] = {};
        #pragma unroll
        for (int k = 0; k < 64; ++k) {
            float w0 = Ws[k * 128 + j];
            #pragma unroll
            for (int r = 0; r < 4; ++r)
                acc[r] = fmaf(xs[(rbase + r) * 64 + k], w0, acc[r]);
        }
        #pragma unroll
        for (int r = 0; r < 4; ++r) {
            int n = row0 + rbase + r;
            if (n < N) out[(size_t)n * 128 + j] = acc[r] + bj;
        }
    }
}

// ---------------- launch ----------------
extern "C" void kernel_launch(void* const* d_in, const int* in_sizes, int n_in,
                              void* d_out, int out_size) {
    const float* features = (const float*)d_in[0];
    const int*   src      = (const int*)  d_in[1];
    const int*   dst      = (const int*)  d_in[2];
    const float* eps      = (const float*)d_in[3];
    const float* W1       = (const float*)d_in[4];
    const float* b1       = (const float*)d_in[5];
    const float* W2       = (const float*)d_in[6];
    const float* b2       = (const float*)d_in[7];
    const float* W3       = (const float*)d_in[8];
    const float* b3       = (const float*)d_in[9];

    int N = in_sizes[0] / 128;
    int E = in_sizes[1];

    float* out   = (float*)d_out;
    float* recon = out;
    float* mean  = out + (size_t)N * 128;
    float* logv  = mean + (size_t)N * 64;

    const int SMEM_G1 = (128 * 256 + 64 * 128) * 4;  // 160KB
    const int SMEM_G2 = (256 * 128 + 64 * 256) * 4;  // 192KB
    const int SMEM_G3 = (64 * 128 + 64 * 64) * 4;    // 48KB
    cudaFuncSetAttribute(gemm1_kernel, cudaFuncAttributeMaxDynamicSharedMemorySize, SMEM_G1);
    cudaFuncSetAttribute(gemm2_kernel, cudaFuncAttributeMaxDynamicSharedMemorySize, SMEM_G2);
    cudaFuncSetAttribute(gemm3_kernel, cudaFuncAttributeMaxDynamicSharedMemorySize, SMEM_G3);

    int gemm_grid = (N + 63) / 64;
    int nb = (N + SCAN_B - 1) / SCAN_B;

    // --- CSR build ---
    zero_small<<<(N + 255) / 256, 256>>>(N);
    hist_kernel<<<(E + 255) / 256, 256>>>(src, dst, E);
    rsqrt_kernel<<<(N + 255) / 256, 256>>>(N);
    scan_part<<<nb, SCAN_B>>>(N);
    scan_tops<<<1, 32>>>(nb);
    scan_add<<<(N + 255) / 256, 256>>>(N, E);
    fill_kernel<<<(E + 255) / 256, 256>>>(src, dst, E);

    // --- layer 1 ---
    gather_d128_l1<<<(N * 32 + 255) / 256, 256>>>(features, N);
    gemm1_kernel<<<gemm_grid, 256, SMEM_G1>>>(W1, b1, N);

    // --- layer 2 (GEMM before aggregation; VAE epilogue fused into gather) ---
    gemm2_kernel<<<gemm_grid, 256, SMEM_G2>>>(W2, N);
    gather_d128_l2_vae<<<(N * 32 + 255) / 256, 256>>>(b2, eps, mean, logv, N);

    // --- layer 3 ---
    gather_d64_l3<<<(N * 16 + 255) / 256, 256>>>(N);
    gemm3_kernel<<<gemm_grid, 256, SMEM_G3>>>(W3, b3, recon, N);
}

// round 5
// speedup vs baseline: 2.4827x; 1.4493x over previous
#include <cuda_runtime.h>
#include <cuda_bf16.h>
#include <math.h>

#define MAXN 100000
#define MAXE 1600000
#define SCAN_B 1024

// ---------------- scratch (static device globals only) ----------------
__device__ int   g_cnt_in [MAXN];
__device__ int   g_cnt_out[MAXN];
__device__ int   g_fill   [MAXN];
__device__ int   g_rowptr [MAXN + 1];
__device__ int   g_csr_src[MAXE];
__device__ int   g_blocksums[1024];
__device__ float g_dout[MAXN];
__device__ float g_din [MAXN];
__device__ float g_agg1[(size_t)MAXN * 128];
__device__ float g_h1  [(size_t)MAXN * 256];
__device__ float g_y2  [(size_t)MAXN * 128];
__device__ float g_z   [(size_t)MAXN * 64];
__device__ float g_agg3[(size_t)MAXN * 64];

// split-bf16 transposed weights: W^T stored [n][k], hi + lo planes
__device__ __nv_bfloat16 g_w1t_hi[256 * 128], g_w1t_lo[256 * 128];
__device__ __nv_bfloat16 g_w2t_hi[128 * 256], g_w2t_lo[128 * 256];
__device__ __nv_bfloat16 g_w3t_hi[128 * 64],  g_w3t_lo[128 * 64];

// ---------------- helpers ----------------
__device__ __forceinline__ void mma_bf16(float* c, const unsigned* a, unsigned b0, unsigned b1) {
    asm volatile(
        "mma.sync.aligned.m16n8k16.row.col.f32.bf16.bf16.f32 "
        "{%0,%1,%2,%3}, {%4,%5,%6,%7}, {%8,%9}, {%0,%1,%2,%3};\n"
        : "+f"(c[0]), "+f"(c[1]), "+f"(c[2]), "+f"(c[3])
        : "r"(a[0]), "r"(a[1]), "r"(a[2]), "r"(a[3]), "r"(b0), "r"(b1));
}

__device__ __forceinline__ void split2(float v, __nv_bfloat16& h, __nv_bfloat16& l) {
    h = __float2bfloat16(v);
    l = __float2bfloat16(v - __bfloat162float(h));
}

// ---------------- weight preprocessing ----------------
__global__ void split_weights(const float* __restrict__ W1, const float* __restrict__ W2,
                              const float* __restrict__ W3) {
    int i = blockIdx.x * blockDim.x + threadIdx.x;
    if (i < 128 * 256) {                 // W1 [k=128][n=256] -> T[n][k]
        int k = i >> 8, n = i & 255;
        split2(W1[i], g_w1t_hi[n * 128 + k], g_w1t_lo[n * 128 + k]);
    }
    if (i < 256 * 128) {                 // W2 [k=256][n=128] -> T[n][k]
        int k = i >> 7, n = i & 127;
        split2(W2[i], g_w2t_hi[n * 256 + k], g_w2t_lo[n * 256 + k]);
    }
    if (i < 64 * 128) {                  // W3 [k=64][n=128] -> T[n][k]
        int k = i >> 7, n = i & 127;
        split2(W3[i], g_w3t_hi[n * 64 + k], g_w3t_lo[n * 64 + k]);
    }
}

// ---------------- CSR build ----------------
__global__ void zero_small(int N) {
    int i = blockIdx.x * blockDim.x + threadIdx.x;
    if (i < N) { g_cnt_in[i] = 0; g_cnt_out[i] = 0; g_fill[i] = 0; }
}

__global__ void hist_kernel(const int* __restrict__ src, const int* __restrict__ dst, int E) {
    int i = blockIdx.x * blockDim.x + threadIdx.x;
    if (i >= E) return;
    atomicAdd(&g_cnt_out[src[i]], 1);
    atomicAdd(&g_cnt_in [dst[i]], 1);
}

__global__ void rsqrt_kernel(int N) {
    int i = blockIdx.x * blockDim.x + threadIdx.x;
    if (i >= N) return;
    g_dout[i] = rsqrtf((float)max(g_cnt_out[i], 1));
    g_din [i] = rsqrtf((float)max(g_cnt_in [i], 1));
}

__global__ void scan_part(int N) {
    __shared__ int sm[SCAN_B];
    int tid = threadIdx.x;
    int i = blockIdx.x * SCAN_B + tid;
    int v = (i < N) ? g_cnt_in[i] : 0;
    sm[tid] = v;
    __syncthreads();
    #pragma unroll
    for (int off = 1; off < SCAN_B; off <<= 1) {
        int t = (tid >= off) ? sm[tid - off] : 0;
        __syncthreads();
        sm[tid] += t;
        __syncthreads();
    }
    if (i < N) g_rowptr[i] = sm[tid] - v;
    if (tid == SCAN_B - 1) g_blocksums[blockIdx.x] = sm[tid];
}

__global__ void scan_tops(int nb) {
    if (threadIdx.x == 0) {
        int acc = 0;
        for (int b = 0; b < nb; ++b) { int t = g_blocksums[b]; g_blocksums[b] = acc; acc += t; }
    }
}

__global__ void scan_add(int N, int E) {
    int i = blockIdx.x * blockDim.x + threadIdx.x;
    if (i < N) g_rowptr[i] += g_blocksums[i / SCAN_B];
    if (i == 0) g_rowptr[N] = E;
}

__global__ void fill_kernel(const int* __restrict__ src, const int* __restrict__ dst, int E) {
    int i = blockIdx.x * blockDim.x + threadIdx.x;
    if (i >= E) return;
    int d = dst[i];
    int pos = g_rowptr[d] + atomicAdd(&g_fill[d], 1);
    g_csr_src[pos] = src[i];
}

// ---------------- gathers (atomic-free CSR) ----------------
__global__ void gather_d128_l1(const float* __restrict__ x, int N) {
    int t = blockIdx.x * blockDim.x + threadIdx.x;
    int node = t >> 5, lane = t & 31;
    if (node >= N) return;
    int beg = g_rowptr[node], end = g_rowptr[node + 1];
    const float4* x4 = reinterpret_cast<const float4*>(x);
    float4 acc = make_float4(0.f, 0.f, 0.f, 0.f);
    #pragma unroll 4
    for (int k = beg; k < end; ++k) {
        int s = __ldg(g_csr_src + k);
        float w = __ldg(g_dout + s);
        float4 v = __ldg(x4 + (size_t)s * 32 + lane);
        acc.x = fmaf(w, v.x, acc.x);
        acc.y = fmaf(w, v.y, acc.y);
        acc.z = fmaf(w, v.z, acc.z);
        acc.w = fmaf(w, v.w, acc.w);
    }
    float di = g_din[node];
    acc.x *= di; acc.y *= di; acc.z *= di; acc.w *= di;
    reinterpret_cast<float4*>(g_agg1)[(size_t)node * 32 + lane] = acc;
}

__global__ void gather_d128_l2_vae(const float* __restrict__ b2, const float* __restrict__ eps,
                                   float* __restrict__ out_mean, float* __restrict__ out_lv, int N) {
    int t = blockIdx.x * blockDim.x + threadIdx.x;
    int node = t >> 5, lane = t & 31;
    if (node >= N) return;
    int beg = g_rowptr[node], end = g_rowptr[node + 1];
    const float4* y4 = reinterpret_cast<const float4*>(g_y2);
    float4 acc = make_float4(0.f, 0.f, 0.f, 0.f);
    #pragma unroll 4
    for (int k = beg; k < end; ++k) {
        int s = __ldg(g_csr_src + k);
        float4 v = __ldg(y4 + (size_t)s * 32 + lane);
        acc.x += v.x; acc.y += v.y; acc.z += v.z; acc.w += v.w;
    }
    float di = g_din[node];
    float4 bb = __ldg(reinterpret_cast<const float4*>(b2) + lane);
    acc.x = fmaf(acc.x, di, bb.x);
    acc.y = fmaf(acc.y, di, bb.y);
    acc.z = fmaf(acc.z, di, bb.z);
    acc.w = fmaf(acc.w, di, bb.w);
    float4 other;
    other.x = __shfl_xor_sync(0xffffffffu, acc.x, 16);
    other.y = __shfl_xor_sync(0xffffffffu, acc.y, 16);
    other.z = __shfl_xor_sync(0xffffffffu, acc.z, 16);
    other.w = __shfl_xor_sync(0xffffffffu, acc.w, 16);
    if (lane < 16) {
        size_t o = (size_t)node * 16 + lane;
        reinterpret_cast<float4*>(out_mean)[o] = acc;
        float4 e = __ldg(reinterpret_cast<const float4*>(eps) + o);
        float4 z;
        z.x = fmaf(e.x, expf(0.5f * other.x), acc.x);
        z.y = fmaf(e.y, expf(0.5f * other.y), acc.y);
        z.z = fmaf(e.z, expf(0.5f * other.z), acc.z);
        z.w = fmaf(e.w, expf(0.5f * other.w), acc.w);
        reinterpret_cast<float4*>(g_z)[o] = z;
    } else {
        reinterpret_cast<float4*>(out_lv)[(size_t)node * 16 + (lane - 16)] = acc;
    }
}

__global__ void gather_d64_l3(int N) {
    int t = blockIdx.x * blockDim.x + threadIdx.x;
    int node = t >> 4, lane = t & 15;
    if (node >= N) return;
    int beg = g_rowptr[node], end = g_rowptr[node + 1];
    const float4* z4 = reinterpret_cast<const float4*>(g_z);
    float4 acc = make_float4(0.f, 0.f, 0.f, 0.f);
    #pragma unroll 4
    for (int k = beg; k < end; ++k) {
        int s = __ldg(g_csr_src + k);
        float w = __ldg(g_dout + s);
        float4 v = __ldg(z4 + (size_t)s * 16 + lane);
        acc.x = fmaf(w, v.x, acc.x);
        acc.y = fmaf(w, v.y, acc.y);
        acc.z = fmaf(w, v.z, acc.z);
        acc.w = fmaf(w, v.w, acc.w);
    }
    float di = g_din[node];
    acc.x *= di; acc.y *= di; acc.z *= di; acc.w *= di;
    reinterpret_cast<float4*>(g_agg3)[(size_t)node * 16 + lane] = acc;
}

// ============================================================================
// Tensor-core GEMMs: mma.sync m16n8k16 bf16, 2-term split (hi/lo) of both
// operands, fp32 accumulate. acc = Ah*Bh + Ah*Bl + Al*Bh  (err ~1.5e-5).
// Smem strides padded to K+8 bf16 (16B row offset in bank space -> no conflicts
// on fragment loads). Block = 256 threads (8 warps), 64 output rows per block.
// ============================================================================

// A-fragment loader: row-major bf16 plane, stride S elems.
#define LOAD_A(frag, plane, rowb, kk, S)                                          \
    {                                                                             \
        int _o = (rowb) * (S) + (kk);                                             \
        frag[0] = *(const unsigned*)((plane) + _o);                               \
        frag[1] = *(const unsigned*)((plane) + _o + 8 * (S));                     \
        frag[2] = *(const unsigned*)((plane) + _o + 8);                           \
        frag[3] = *(const unsigned*)((plane) + _o + 8 * (S) + 8);                 \
    }

// ---------------- GEMM1: h1 = relu(agg1[128] @ W1 -> 256 cols) ----------------
__global__ void gemm1_mma(const float* __restrict__ bias, int N) {
    const int K = 128, S = 136;
    extern __shared__ __nv_bfloat16 sm[];
    __nv_bfloat16* xh = sm;                 // 64*136
    __nv_bfloat16* xl = xh + 64 * S;
    __nv_bfloat16* wh = xl + 64 * S;        // 256*136
    __nv_bfloat16* wl = wh + 256 * S;
    int tid = threadIdx.x;
    int row0 = blockIdx.x * 64;

    // stage W^T (256 rows x 128 k) as uint copies with repad
    {
        const unsigned* sh = (const unsigned*)g_w1t_hi;
        const unsigned* sl = (const unsigned*)g_w1t_lo;
        unsigned* dh = (unsigned*)wh;
        unsigned* dl = (unsigned*)wl;
        for (int j = tid; j < 256 * 64; j += 256) {
            int r = j >> 6, c2 = j & 63;
            dh[r * 68 + c2] = sh[j];
            dl[r * 68 + c2] = sl[j];
        }
    }
    // stage x (split)
    for (int i = tid; i < 64 * 32; i += 256) {
        int r = i >> 5, c4 = i & 31;
        int n = row0 + r;
        float4 v = make_float4(0.f, 0.f, 0.f, 0.f);
        if (n < N) v = ((const float4*)g_agg1)[(size_t)n * 32 + c4];
        float vv[4] = {v.x, v.y, v.z, v.w};
        #pragma unroll
        for (int j = 0; j < 4; ++j)
            split2(vv[j], xh[r * S + c4 * 4 + j], xl[r * S + c4 * 4 + j]);
    }
    __syncthreads();

    int wid = tid >> 5, lane = tid & 31;
    int g = lane >> 2, t2 = (lane & 3) * 2;
    int wr = wid & 1, wc = wid >> 1;      // warp = 32 rows x 64 cols

    float acc[2][8][4];
    #pragma unroll
    for (int a = 0; a < 2; ++a)
        #pragma unroll
        for (int b = 0; b < 8; ++b)
            #pragma unroll
            for (int c = 0; c < 4; ++c) acc[a][b][c] = 0.f;

    for (int k0 = 0; k0 < K; k0 += 16) {
        unsigned ah[2][4], al[2][4];
        #pragma unroll
        for (int mt = 0; mt < 2; ++mt) {
            int rb = wr * 32 + mt * 16 + g;
            LOAD_A(ah[mt], xh, rb, k0 + t2, S);
            LOAD_A(al[mt], xl, rb, k0 + t2, S);
        }
        #pragma unroll
        for (int nt = 0; nt < 8; ++nt) {
            int bo = (wc * 64 + nt * 8 + g) * S + k0 + t2;
            unsigned bh0 = *(const unsigned*)(wh + bo);
            unsigned bh1 = *(const unsigned*)(wh + bo + 8);
            unsigned bl0 = *(const unsigned*)(wl + bo);
            unsigned bl1 = *(const unsigned*)(wl + bo + 8);
            #pragma unroll
            for (int mt = 0; mt < 2; ++mt) {
                mma_bf16(acc[mt][nt], ah[mt], bh0, bh1);
                mma_bf16(acc[mt][nt], ah[mt], bl0, bl1);
                mma_bf16(acc[mt][nt], al[mt], bh0, bh1);
            }
        }
    }
    // epilogue: + bias, relu
    #pragma unroll
    for (int nt = 0; nt < 8; ++nt) {
        int col = wc * 64 + nt * 8 + t2;
        float b0 = __ldg(bias + col), b1v = __ldg(bias + col + 1);
        #pragma unroll
        for (int mt = 0; mt < 2; ++mt) {
            int r0 = row0 + wr * 32 + mt * 16 + g;
            if (r0 < N) {
                g_h1[(size_t)r0 * 256 + col]     = fmaxf(acc[mt][nt][0] + b0, 0.f);
                g_h1[(size_t)r0 * 256 + col + 1] = fmaxf(acc[mt][nt][1] + b1v, 0.f);
            }
            int r1 = r0 + 8;
            if (r1 < N) {
                g_h1[(size_t)r1 * 256 + col]     = fmaxf(acc[mt][nt][2] + b0, 0.f);
                g_h1[(size_t)r1 * 256 + col + 1] = fmaxf(acc[mt][nt][3] + b1v, 0.f);
            }
        }
    }
}

// ---------------- GEMM2: y2 = (h1[256]*dout) @ W2 -> 128 cols ----------------
__global__ void gemm2_mma(int N) {
    const int K = 256, S = 264;
    extern __shared__ __nv_bfloat16 sm[];
    __nv_bfloat16* xh = sm;                 // 64*264
    __nv_bfloat16* xl = xh + 64 * S;
    __nv_bfloat16* wh = xl + 64 * S;        // 128*264
    __nv_bfloat16* wl = wh + 128 * S;
    int tid = threadIdx.x;
    int row0 = blockIdx.x * 64;

    {
        const unsigned* sh = (const unsigned*)g_w2t_hi;
        const unsigned* sl = (const unsigned*)g_w2t_lo;
        unsigned* dh = (unsigned*)wh;
        unsigned* dl = (unsigned*)wl;
        for (int j = tid; j < 128 * 128; j += 256) {
            int r = j >> 7, c2 = j & 127;
            dh[r * 132 + c2] = sh[j];
            dl[r * 132 + c2] = sl[j];
        }
    }
    for (int i = tid; i < 64 * 64; i += 256) {
        int r = i >> 6, c4 = i & 63;
        int n = row0 + r;
        float4 v = make_float4(0.f, 0.f, 0.f, 0.f);
        if (n < N) {
            v = ((const float4*)g_h1)[(size_t)n * 64 + c4];
            float s = g_dout[n];
            v.x *= s; v.y *= s; v.z *= s; v.w *= s;
        }
        float vv[4] = {v.x, v.y, v.z, v.w};
        #pragma unroll
        for (int j = 0; j < 4; ++j)
            split2(vv[j], xh[r * S + c4 * 4 + j], xl[r * S + c4 * 4 + j]);
    }
    __syncthreads();

    int wid = tid >> 5, lane = tid & 31;
    int g = lane >> 2, t2 = (lane & 3) * 2;
    int wr = wid & 1, wc = wid >> 1;      // warp = 32 rows x 32 cols

    float acc[2][4][4];
    #pragma unroll
    for (int a = 0; a < 2; ++a)
        #pragma unroll
        for (int b = 0; b < 4; ++b)
            #pragma unroll
            for (int c = 0; c < 4; ++c) acc[a][b][c] = 0.f;

    for (int k0 = 0; k0 < K; k0 += 16) {
        unsigned ah[2][4], al[2][4];
        #pragma unroll
        for (int mt = 0; mt < 2; ++mt) {
            int rb = wr * 32 + mt * 16 + g;
            LOAD_A(ah[mt], xh, rb, k0 + t2, S);
            LOAD_A(al[mt], xl, rb, k0 + t2, S);
        }
        #pragma unroll
        for (int nt = 0; nt < 4; ++nt) {
            int bo = (wc * 32 + nt * 8 + g) * S + k0 + t2;
            unsigned bh0 = *(const unsigned*)(wh + bo);
            unsigned bh1 = *(const unsigned*)(wh + bo + 8);
            unsigned bl0 = *(const unsigned*)(wl + bo);
            unsigned bl1 = *(const unsigned*)(wl + bo + 8);
            #pragma unroll
            for (int mt = 0; mt < 2; ++mt) {
                mma_bf16(acc[mt][nt], ah[mt], bh0, bh1);
                mma_bf16(acc[mt][nt], ah[mt], bl0, bl1);
                mma_bf16(acc[mt][nt], al[mt], bh0, bh1);
            }
        }
    }
    #pragma unroll
    for (int nt = 0; nt < 4; ++nt) {
        int col = wc * 32 + nt * 8 + t2;
        #pragma unroll
        for (int mt = 0; mt < 2; ++mt) {
            int r0 = row0 + wr * 32 + mt * 16 + g;
            if (r0 < N) {
                g_y2[(size_t)r0 * 128 + col]     = acc[mt][nt][0];
                g_y2[(size_t)r0 * 128 + col + 1] = acc[mt][nt][1];
            }
            int r1 = r0 + 8;
            if (r1 < N) {
                g_y2[(size_t)r1 * 128 + col]     = acc[mt][nt][2];
                g_y2[(size_t)r1 * 128 + col + 1] = acc[mt][nt][3];
            }
        }
    }
}

// ---------------- GEMM3: recon = agg3[64] @ W3 -> 128 cols + b3 ----------------
__global__ void gemm3_mma(const float* __restrict__ bias, float* __restrict__ out, int N) {
    const int K = 64, S = 72;
    extern __shared__ __nv_bfloat16 sm[];
    __nv_bfloat16* xh = sm;                 // 64*72
    __nv_bfloat16* xl = xh + 64 * S;
    __nv_bfloat16* wh = xl + 64 * S;        // 128*72
    __nv_bfloat16* wl = wh + 128 * S;
    int tid = threadIdx.x;
    int row0 = blockIdx.x * 64;

    {
        const unsigned* sh = (const unsigned*)g_w3t_hi;
        const unsigned* sl = (const unsigned*)g_w3t_lo;
        unsigned* dh = (unsigned*)wh;
        unsigned* dl = (unsigned*)wl;
        for (int j = tid; j < 128 * 32; j += 256) {
            int r = j >> 5, c2 = j & 31;
            dh[r * 36 + c2] = sh[j];
            dl[r * 36 + c2] = sl[j];
        }
    }
    for (int i = tid; i < 64 * 16; i += 256) {
        int r = i >> 4, c4 = i & 15;
        int n = row0 + r;
        float4 v = make_float4(0.f, 0.f, 0.f, 0.f);
        if (n < N) v = ((const float4*)g_agg3)[(size_t)n * 16 + c4];
        float vv[4] = {v.x, v.y, v.z, v.w};
        #pragma unroll
        for (int j = 0; j < 4; ++j)
            split2(vv[j], xh[r * S + c4 * 4 + j], xl[r * S + c4 * 4 + j]);
    }
    __syncthreads();

    int wid = tid >> 5, lane = tid & 31;
    int g = lane >> 2, t2 = (lane & 3) * 2;
    int wr = wid & 1, wc = wid >> 1;

    float acc[2][4][4];
    #pragma unroll
    for (int a = 0; a < 2; ++a)
        #pragma unroll
        for (int b = 0; b < 4; ++b)
            #pragma unroll
            for (int c = 0; c < 4; ++c) acc[a][b][c] = 0.f;

    #pragma unroll
    for (int k0 = 0; k0 < K; k0 += 16) {
        unsigned ah[2][4], al[2][4];
        #pragma unroll
        for (int mt = 0; mt < 2; ++mt) {
            int rb = wr * 32 + mt * 16 + g;
            LOAD_A(ah[mt], xh, rb, k0 + t2, S);
            LOAD_A(al[mt], xl, rb, k0 + t2, S);
        }
        #pragma unroll
        for (int nt = 0; nt < 4; ++nt) {
            int bo = (wc * 32 + nt * 8 + g) * S + k0 + t2;
            unsigned bh0 = *(const unsigned*)(wh + bo);
            unsigned bh1 = *(const unsigned*)(wh + bo + 8);
            unsigned bl0 = *(const unsigned*)(wl + bo);
            unsigned bl1 = *(const unsigned*)(wl + bo + 8);
            #pragma unroll
            for (int mt = 0; mt < 2; ++mt) {
                mma_bf16(acc[mt][nt], ah[mt], bh0, bh1);
                mma_bf16(acc[mt][nt], ah[mt], bl0, bl1);
                mma_bf16(acc[mt][nt], al[mt], bh0, bh1);
            }
        }
    }
    #pragma unroll
    for (int nt = 0; nt < 4; ++nt) {
        int col = wc * 32 + nt * 8 + t2;
        float b0 = __ldg(bias + col), b1v = __ldg(bias + col + 1);
        #pragma unroll
        for (int mt = 0; mt < 2; ++mt) {
            int r0 = row0 + wr * 32 + mt * 16 + g;
            if (r0 < N) {
                out[(size_t)r0 * 128 + col]     = acc[mt][nt][0] + b0;
                out[(size_t)r0 * 128 + col + 1] = acc[mt][nt][1] + b1v;
            }
            int r1 = r0 + 8;
            if (r1 < N) {
                out[(size_t)r1 * 128 + col]     = acc[mt][nt][2] + b0;
                out[(size_t)r1 * 128 + col + 1] = acc[mt][nt][3] + b1v;
            }
        }
    }
}

// ---------------- launch ----------------
extern "C" void kernel_launch(void* const* d_in, const int* in_sizes, int n_in,
                              void* d_out, int out_size) {
    const float* features = (const float*)d_in[0];
    const int*   src      = (const int*)  d_in[1];
    const int*   dst      = (const int*)  d_in[2];
    const float* eps      = (const float*)d_in[3];
    const float* W1       = (const float*)d_in[4];
    const float* b1       = (const float*)d_in[5];
    const float* W2       = (const float*)d_in[6];
    const float* b2       = (const float*)d_in[7];
    const float* W3       = (const float*)d_in[8];
    const float* b3       = (const float*)d_in[9];

    int N = in_sizes[0] / 128;
    int E = in_sizes[1];

    float* out   = (float*)d_out;
    float* recon = out;
    float* mean  = out + (size_t)N * 128;
    float* logv  = mean + (size_t)N * 64;

    const int SMEM_G1 = (64 * 136 * 2 + 256 * 136 * 2) * 2;   // ~174KB
    const int SMEM_G2 = (64 * 264 * 2 + 128 * 264 * 2) * 2;   // ~203KB
    const int SMEM_G3 = (64 * 72 * 2 + 128 * 72 * 2) * 2;     // ~55KB
    cudaFuncSetAttribute(gemm1_mma, cudaFuncAttributeMaxDynamicSharedMemorySize, SMEM_G1);
    cudaFuncSetAttribute(gemm2_mma, cudaFuncAttributeMaxDynamicSharedMemorySize, SMEM_G2);
    cudaFuncSetAttribute(gemm3_mma, cudaFuncAttributeMaxDynamicSharedMemorySize, SMEM_G3);

    int gemm_grid = (N + 63) / 64;
    int nb = (N + SCAN_B - 1) / SCAN_B;

    split_weights<<<(256 * 128 + 255) / 256, 256>>>(W1, W2, W3);

    zero_small<<<(N + 255) / 256, 256>>>(N);
    hist_kernel<<<(E + 255) / 256, 256>>>(src, dst, E);
    rsqrt_kernel<<<(N + 255) / 256, 256>>>(N);
    scan_part<<<nb, SCAN_B>>>(N);
    scan_tops<<<1, 32>>>(nb);
    scan_add<<<(N + 255) / 256, 256>>>(N, E);
    fill_kernel<<<(E + 255) / 256, 256>>>(src, dst, E);

    gather_d128_l1<<<(N * 32 + 255) / 256, 256>>>(features, N);
    gemm1_mma<<<gemm_grid, 256, SMEM_G1>>>(b1, N);

    gemm2_mma<<<gemm_grid, 256, SMEM_G2>>>(N);
    gather_d128_l2_vae<<<(N * 32 + 255) / 256, 256>>>(b2, eps, mean, logv, N);

    gather_d64_l3<<<(N * 16 + 255) / 256, 256>>>(N);
    gemm3_mma<<<gemm_grid, 256, SMEM_G3>>>(b3, recon, N);
}

// round 6
// speedup vs baseline: 3.6781x; 1.4815x over previous
#include <cuda_runtime.h>
#include <cuda_bf16.h>
#include <math.h>

#define MAXN 100000
#define MAXE 1600000
#define SCAN_B 1024

// ---------------- scratch (static device globals only) ----------------
__device__ int   g_cnt_in [MAXN];
__device__ int   g_cnt_out[MAXN];
__device__ int   g_fill   [MAXN];
__device__ int   g_rowptr [MAXN + 1];
__device__ int   g_csr_src[MAXE];
__device__ int   g_blocksums[1024];
__device__ float g_dout[MAXN];
__device__ float g_din [MAXN];
__device__ float g_agg1[(size_t)MAXN * 128];
__device__ float g_h1  [(size_t)MAXN * 256];
__device__ float g_y2  [(size_t)MAXN * 128];
__device__ float g_z   [(size_t)MAXN * 64];
__device__ float g_agg3[(size_t)MAXN * 64];

// split-bf16 transposed weights: W^T stored [n][k], hi + lo planes
__device__ __nv_bfloat16 g_w1t_hi[256 * 128], g_w1t_lo[256 * 128];
__device__ __nv_bfloat16 g_w2t_hi[128 * 256], g_w2t_lo[128 * 256];
__device__ __nv_bfloat16 g_w3t_hi[128 * 64],  g_w3t_lo[128 * 64];

// ---------------- helpers ----------------
__device__ __forceinline__ void mma_bf16(float* c, const unsigned* a, unsigned b0, unsigned b1) {
    asm volatile(
        "mma.sync.aligned.m16n8k16.row.col.f32.bf16.bf16.f32 "
        "{%0,%1,%2,%3}, {%4,%5,%6,%7}, {%8,%9}, {%0,%1,%2,%3};\n"
        : "+f"(c[0]), "+f"(c[1]), "+f"(c[2]), "+f"(c[3])
        : "r"(a[0]), "r"(a[1]), "r"(a[2]), "r"(a[3]), "r"(b0), "r"(b1));
}

__device__ __forceinline__ void split2(float v, __nv_bfloat16& h, __nv_bfloat16& l) {
    h = __float2bfloat16(v);
    l = __float2bfloat16(v - __bfloat162float(h));
}

// ---------------- weight preprocessing ----------------
__global__ void split_weights(const float* __restrict__ W1, const float* __restrict__ W2,
                              const float* __restrict__ W3) {
    int i = blockIdx.x * blockDim.x + threadIdx.x;
    if (i < 128 * 256) {                 // W1 [k=128][n=256] -> T[n][k]
        int k = i >> 8, n = i & 255;
        split2(W1[i], g_w1t_hi[n * 128 + k], g_w1t_lo[n * 128 + k]);
    }
    if (i < 256 * 128) {                 // W2 [k=256][n=128] -> T[n][k]
        int k = i >> 7, n = i & 127;
        split2(W2[i], g_w2t_hi[n * 256 + k], g_w2t_lo[n * 256 + k]);
    }
    if (i < 64 * 128) {                  // W3 [k=64][n=128] -> T[n][k]
        int k = i >> 7, n = i & 127;
        split2(W3[i], g_w3t_hi[n * 64 + k], g_w3t_lo[n * 64 + k]);
    }
}

// ---------------- CSR build ----------------
__global__ void zero_small(int N) {
    int i = blockIdx.x * blockDim.x + threadIdx.x;
    if (i < N) { g_cnt_in[i] = 0; g_cnt_out[i] = 0; g_fill[i] = 0; }
}

__global__ void hist_kernel(const int* __restrict__ src, const int* __restrict__ dst, int E) {
    int i = (blockIdx.x * blockDim.x + threadIdx.x) * 4;
    if (i + 3 < E) {
        int4 s = *reinterpret_cast<const int4*>(src + i);
        int4 d = *reinterpret_cast<const int4*>(dst + i);
        atomicAdd(&g_cnt_out[s.x], 1); atomicAdd(&g_cnt_out[s.y], 1);
        atomicAdd(&g_cnt_out[s.z], 1); atomicAdd(&g_cnt_out[s.w], 1);
        atomicAdd(&g_cnt_in [d.x], 1); atomicAdd(&g_cnt_in [d.y], 1);
        atomicAdd(&g_cnt_in [d.z], 1); atomicAdd(&g_cnt_in [d.w], 1);
    } else {
        for (; i < E; ++i) {
            atomicAdd(&g_cnt_out[src[i]], 1);
            atomicAdd(&g_cnt_in [dst[i]], 1);
        }
    }
}

__global__ void scan_part(int N) {
    __shared__ int sm[SCAN_B];
    int tid = threadIdx.x;
    int i = blockIdx.x * SCAN_B + tid;
    int v = (i < N) ? g_cnt_in[i] : 0;
    sm[tid] = v;
    __syncthreads();
    #pragma unroll
    for (int off = 1; off < SCAN_B; off <<= 1) {
        int t = (tid >= off) ? sm[tid - off] : 0;
        __syncthreads();
        sm[tid] += t;
        __syncthreads();
    }
    if (i < N) g_rowptr[i] = sm[tid] - v;
    if (tid == SCAN_B - 1) g_blocksums[blockIdx.x] = sm[tid];
}

__global__ void scan_tops(int nb) {
    if (threadIdx.x == 0) {
        int acc = 0;
        for (int b = 0; b < nb; ++b) { int t = g_blocksums[b]; g_blocksums[b] = acc; acc += t; }
    }
}

// scan finalize + rsqrt degrees (merged)
__global__ void scan_add(int N, int E) {
    int i = blockIdx.x * blockDim.x + threadIdx.x;
    if (i < N) {
        g_rowptr[i] += g_blocksums[i / SCAN_B];
        g_dout[i] = rsqrtf((float)max(g_cnt_out[i], 1));
        g_din [i] = rsqrtf((float)max(g_cnt_in [i], 1));
    }
    if (i == 0) g_rowptr[N] = E;
}

__global__ void fill_kernel(const int* __restrict__ src, const int* __restrict__ dst, int E) {
    int i = blockIdx.x * blockDim.x + threadIdx.x;
    if (i >= E) return;
    int d = dst[i];
    int pos = g_rowptr[d] + atomicAdd(&g_fill[d], 1);
    g_csr_src[pos] = src[i];
}

// ---------------- gathers (atomic-free CSR) ----------------
__global__ void gather_d128_l1(const float* __restrict__ x, int N) {
    int t = blockIdx.x * blockDim.x + threadIdx.x;
    int node = t >> 5, lane = t & 31;
    if (node >= N) return;
    int beg = g_rowptr[node], end = g_rowptr[node + 1];
    const float4* x4 = reinterpret_cast<const float4*>(x);
    float4 acc = make_float4(0.f, 0.f, 0.f, 0.f);
    #pragma unroll 4
    for (int k = beg; k < end; ++k) {
        int s = __ldg(g_csr_src + k);
        float w = __ldg(g_dout + s);
        float4 v = __ldg(x4 + (size_t)s * 32 + lane);
        acc.x = fmaf(w, v.x, acc.x);
        acc.y = fmaf(w, v.y, acc.y);
        acc.z = fmaf(w, v.z, acc.z);
        acc.w = fmaf(w, v.w, acc.w);
    }
    float di = g_din[node];
    acc.x *= di; acc.y *= di; acc.z *= di; acc.w *= di;
    reinterpret_cast<float4*>(g_agg1)[(size_t)node * 32 + lane] = acc;
}

__global__ void gather_d128_l2_vae(const float* __restrict__ b2, const float* __restrict__ eps,
                                   float* __restrict__ out_mean, float* __restrict__ out_lv, int N) {
    int t = blockIdx.x * blockDim.x + threadIdx.x;
    int node = t >> 5, lane = t & 31;
    if (node >= N) return;
    int beg = g_rowptr[node], end = g_rowptr[node + 1];
    const float4* y4 = reinterpret_cast<const float4*>(g_y2);
    float4 acc = make_float4(0.f, 0.f, 0.f, 0.f);
    #pragma unroll 4
    for (int k = beg; k < end; ++k) {
        int s = __ldg(g_csr_src + k);
        float4 v = __ldg(y4 + (size_t)s * 32 + lane);
        acc.x += v.x; acc.y += v.y; acc.z += v.z; acc.w += v.w;
    }
    float di = g_din[node];
    float4 bb = __ldg(reinterpret_cast<const float4*>(b2) + lane);
    acc.x = fmaf(acc.x, di, bb.x);
    acc.y = fmaf(acc.y, di, bb.y);
    acc.z = fmaf(acc.z, di, bb.z);
    acc.w = fmaf(acc.w, di, bb.w);
    float4 other;
    other.x = __shfl_xor_sync(0xffffffffu, acc.x, 16);
    other.y = __shfl_xor_sync(0xffffffffu, acc.y, 16);
    other.z = __shfl_xor_sync(0xffffffffu, acc.z, 16);
    other.w = __shfl_xor_sync(0xffffffffu, acc.w, 16);
    if (lane < 16) {
        size_t o = (size_t)node * 16 + lane;
        reinterpret_cast<float4*>(out_mean)[o] = acc;
        float4 e = __ldg(reinterpret_cast<const float4*>(eps) + o);
        float4 z;
        z.x = fmaf(e.x, expf(0.5f * other.x), acc.x);
        z.y = fmaf(e.y, expf(0.5f * other.y), acc.y);
        z.z = fmaf(e.z, expf(0.5f * other.z), acc.z);
        z.w = fmaf(e.w, expf(0.5f * other.w), acc.w);
        reinterpret_cast<float4*>(g_z)[o] = z;
    } else {
        reinterpret_cast<float4*>(out_lv)[(size_t)node * 16 + (lane - 16)] = acc;
    }
}

__global__ void gather_d64_l3(int N) {
    int t = blockIdx.x * blockDim.x + threadIdx.x;
    int node = t >> 4, lane = t & 15;
    if (node >= N) return;
    int beg = g_rowptr[node], end = g_rowptr[node + 1];
    const float4* z4 = reinterpret_cast<const float4*>(g_z);
    float4 acc = make_float4(0.f, 0.f, 0.f, 0.f);
    #pragma unroll 4
    for (int k = beg; k < end; ++k) {
        int s = __ldg(g_csr_src + k);
        float w = __ldg(g_dout + s);
        float4 v = __ldg(z4 + (size_t)s * 16 + lane);
        acc.x = fmaf(w, v.x, acc.x);
        acc.y = fmaf(w, v.y, acc.y);
        acc.z = fmaf(w, v.z, acc.z);
        acc.w = fmaf(w, v.w, acc.w);
    }
    float di = g_din[node];
    acc.x *= di; acc.y *= di; acc.z *= di; acc.w *= di;
    reinterpret_cast<float4*>(g_agg3)[(size_t)node * 16 + lane] = acc;
}

// ============================================================================
// Persistent tensor-core GEMMs. W staged to smem ONCE per CTA, then a loop
// over 64-row tiles with register-prefetch of the next x tile (global-load
// latency hidden under current tile's MMA). Split-bf16 3-term accumulation.
// ============================================================================

#define LOAD_A(frag, plane, rowb, kk, S)                                          \
    {                                                                             \
        int _o = (rowb) * (S) + (kk);                                             \
        frag[0] = *(const unsigned*)((plane) + _o);                               \
        frag[1] = *(const unsigned*)((plane) + _o + 8 * (S));                     \
        frag[2] = *(const unsigned*)((plane) + _o + 8);                           \
        frag[3] = *(const unsigned*)((plane) + _o + 8 * (S) + 8);                 \
    }

// ---------------- GEMM1: h1 = relu(agg1[128] @ W1 -> 256 cols) ----------------
__global__ void gemm1_mma(const float* __restrict__ bias, int N, int ntiles) {
    const int S = 136;
    extern __shared__ __nv_bfloat16 sm[];
    __nv_bfloat16* xh = sm;                 // 64*136
    __nv_bfloat16* xl = xh + 64 * S;
    __nv_bfloat16* wh = xl + 64 * S;        // 256*136
    __nv_bfloat16* wl = wh + 256 * S;
    int tid = threadIdx.x;

    // stage W once per CTA
    {
        const unsigned* sh = (const unsigned*)g_w1t_hi;
        const unsigned* sl = (const unsigned*)g_w1t_lo;
        unsigned* dh = (unsigned*)wh;
        unsigned* dl = (unsigned*)wl;
        for (int j = tid; j < 256 * 64; j += 256) {
            int r = j >> 6, c2 = j & 63;
            dh[r * 68 + c2] = sh[j];
            dl[r * 68 + c2] = sl[j];
        }
    }

    int wid = tid >> 5, lane = tid & 31;
    int g = lane >> 2, t2 = (lane & 3) * 2;
    int wr = wid & 1, wc = wid >> 1;      // warp = 32 rows x 64 cols

    // prefetch first tile
    float4 pf[8];
    int tile = blockIdx.x;
    if (tile < ntiles) {
        int row0 = tile * 64;
        #pragma unroll
        for (int j = 0; j < 8; ++j) {
            int i = tid + j * 256;
            int r = i >> 5, c4 = i & 31;
            int n = row0 + r;
            pf[j] = (n < N) ? __ldg((const float4*)g_agg1 + (size_t)n * 32 + c4)
                            : make_float4(0.f, 0.f, 0.f, 0.f);
        }
    }

    for (; tile < ntiles; tile += gridDim.x) {
        int row0 = tile * 64;
        // split regs -> smem
        #pragma unroll
        for (int j = 0; j < 8; ++j) {
            int i = tid + j * 256;
            int r = i >> 5, c4 = i & 31;
            float vv[4] = {pf[j].x, pf[j].y, pf[j].z, pf[j].w};
            #pragma unroll
            for (int q = 0; q < 4; ++q)
                split2(vv[q], xh[r * S + c4 * 4 + q], xl[r * S + c4 * 4 + q]);
        }
        __syncthreads();

        // prefetch next tile (loads overlap MMA below)
        int tnext = tile + gridDim.x;
        if (tnext < ntiles) {
            int rn0 = tnext * 64;
            #pragma unroll
            for (int j = 0; j < 8; ++j) {
                int i = tid + j * 256;
                int r = i >> 5, c4 = i & 31;
                int n = rn0 + r;
                pf[j] = (n < N) ? __ldg((const float4*)g_agg1 + (size_t)n * 32 + c4)
                                : make_float4(0.f, 0.f, 0.f, 0.f);
            }
        }

        float acc[2][8][4];
        #pragma unroll
        for (int a = 0; a < 2; ++a)
            #pragma unroll
            for (int b = 0; b < 8; ++b)
                #pragma unroll
                for (int c = 0; c < 4; ++c) acc[a][b][c] = 0.f;

        #pragma unroll
        for (int k0 = 0; k0 < 128; k0 += 16) {
            unsigned ah[2][4], al[2][4];
            #pragma unroll
            for (int mt = 0; mt < 2; ++mt) {
                int rb = wr * 32 + mt * 16 + g;
                LOAD_A(ah[mt], xh, rb, k0 + t2, S);
                LOAD_A(al[mt], xl, rb, k0 + t2, S);
            }
            #pragma unroll
            for (int nt = 0; nt < 8; ++nt) {
                int bo = (wc * 64 + nt * 8 + g) * S + k0 + t2;
                unsigned bh0 = *(const unsigned*)(wh + bo);
                unsigned bh1 = *(const unsigned*)(wh + bo + 8);
                unsigned bl0 = *(const unsigned*)(wl + bo);
                unsigned bl1 = *(const unsigned*)(wl + bo + 8);
                #pragma unroll
                for (int mt = 0; mt < 2; ++mt) {
                    mma_bf16(acc[mt][nt], ah[mt], bh0, bh1);
                    mma_bf16(acc[mt][nt], ah[mt], bl0, bl1);
                    mma_bf16(acc[mt][nt], al[mt], bh0, bh1);
                }
            }
        }

        #pragma unroll
        for (int nt = 0; nt < 8; ++nt) {
            int col = wc * 64 + nt * 8 + t2;
            float b0 = __ldg(bias + col), b1v = __ldg(bias + col + 1);
            #pragma unroll
            for (int mt = 0; mt < 2; ++mt) {
                int r0 = row0 + wr * 32 + mt * 16 + g;
                if (r0 < N) {
                    g_h1[(size_t)r0 * 256 + col]     = fmaxf(acc[mt][nt][0] + b0, 0.f);
                    g_h1[(size_t)r0 * 256 + col + 1] = fmaxf(acc[mt][nt][1] + b1v, 0.f);
                }
                int r1 = r0 + 8;
                if (r1 < N) {
                    g_h1[(size_t)r1 * 256 + col]     = fmaxf(acc[mt][nt][2] + b0, 0.f);
                    g_h1[(size_t)r1 * 256 + col + 1] = fmaxf(acc[mt][nt][3] + b1v, 0.f);
                }
            }
        }
        __syncthreads();
    }
}

// ---------------- GEMM2: y2 = dout * (h1[256] @ W2 -> 128 cols) ----------------
__global__ void gemm2_mma(int N, int ntiles) {
    const int S = 264;
    extern __shared__ __nv_bfloat16 sm[];
    __nv_bfloat16* xh = sm;                 // 64*264
    __nv_bfloat16* xl = xh + 64 * S;
    __nv_bfloat16* wh = xl + 64 * S;        // 128*264
    __nv_bfloat16* wl = wh + 128 * S;
    int tid = threadIdx.x;

    {
        const unsigned* sh = (const unsigned*)g_w2t_hi;
        const unsigned* sl = (const unsigned*)g_w2t_lo;
        unsigned* dh = (unsigned*)wh;
        unsigned* dl = (unsigned*)wl;
        for (int j = tid; j < 128 * 128; j += 256) {
            int r = j >> 7, c2 = j & 127;
            dh[r * 132 + c2] = sh[j];
            dl[r * 132 + c2] = sl[j];
        }
    }

    int wid = tid >> 5, lane = tid & 31;
    int g = lane >> 2, t2 = (lane & 3) * 2;
    int wr = wid & 1, wc = wid >> 1;      // warp = 32 rows x 32 cols

    float4 pf[16];
    int tile = blockIdx.x;
    if (tile < ntiles) {
        int row0 = tile * 64;
        #pragma unroll
        for (int j = 0; j < 16; ++j) {
            int i = tid + j * 256;
            int r = i >> 6, c4 = i & 63;
            int n = row0 + r;
            pf[j] = (n < N) ? __ldg((const float4*)g_h1 + (size_t)n * 64 + c4)
                            : make_float4(0.f, 0.f, 0.f, 0.f);
        }
    }

    for (; tile < ntiles; tile += gridDim.x) {
        int row0 = tile * 64;
        #pragma unroll
        for (int j = 0; j < 16; ++j) {
            int i = tid + j * 256;
            int r = i >> 6, c4 = i & 63;
            float vv[4] = {pf[j].x, pf[j].y, pf[j].z, pf[j].w};
            #pragma unroll
            for (int q = 0; q < 4; ++q)
                split2(vv[q], xh[r * S + c4 * 4 + q], xl[r * S + c4 * 4 + q]);
        }
        __syncthreads();

        int tnext = tile + gridDim.x;
        if (tnext < ntiles) {
            int rn0 = tnext * 64;
            #pragma unroll
            for (int j = 0; j < 16; ++j) {
                int i = tid + j * 256;
                int r = i >> 6, c4 = i & 63;
                int n = rn0 + r;
                pf[j] = (n < N) ? __ldg((const float4*)g_h1 + (size_t)n * 64 + c4)
                                : make_float4(0.f, 0.f, 0.f, 0.f);
            }
        }

        float acc[2][4][4];
        #pragma unroll
        for (int a = 0; a < 2; ++a)
            #pragma unroll
            for (int b = 0; b < 4; ++b)
                #pragma unroll
                for (int c = 0; c < 4; ++c) acc[a][b][c] = 0.f;

        #pragma unroll
        for (int k0 = 0; k0 < 256; k0 += 16) {
            unsigned ah[2][4], al[2][4];
            #pragma unroll
            for (int mt = 0; mt < 2; ++mt) {
                int rb = wr * 32 + mt * 16 + g;
                LOAD_A(ah[mt], xh, rb, k0 + t2, S);
                LOAD_A(al[mt], xl, rb, k0 + t2, S);
            }
            #pragma unroll
            for (int nt = 0; nt < 4; ++nt) {
                int bo = (wc * 32 + nt * 8 + g) * S + k0 + t2;
                unsigned bh0 = *(const unsigned*)(wh + bo);
                unsigned bh1 = *(const unsigned*)(wh + bo + 8);
                unsigned bl0 = *(const unsigned*)(wl + bo);
                unsigned bl1 = *(const unsigned*)(wl + bo + 8);
                #pragma unroll
                for (int mt = 0; mt < 2; ++mt) {
                    mma_bf16(acc[mt][nt], ah[mt], bh0, bh1);
                    mma_bf16(acc[mt][nt], ah[mt], bl0, bl1);
                    mma_bf16(acc[mt][nt], al[mt], bh0, bh1);
                }
            }
        }

        // epilogue: scale by dout[row] (reordered-layer fold)
        #pragma unroll
        for (int nt = 0; nt < 4; ++nt) {
            int col = wc * 32 + nt * 8 + t2;
            #pragma unroll
            for (int mt = 0; mt < 2; ++mt) {
                int r0 = row0 + wr * 32 + mt * 16 + g;
                if (r0 < N) {
                    float s0 = __ldg(g_dout + r0);
                    g_y2[(size_t)r0 * 128 + col]     = acc[mt][nt][0] * s0;
                    g_y2[(size_t)r0 * 128 + col + 1] = acc[mt][nt][1] * s0;
                }
                int r1 = r0 + 8;
                if (r1 < N) {
                    float s1 = __ldg(g_dout + r1);
                    g_y2[(size_t)r1 * 128 + col]     = acc[mt][nt][2] * s1;
                    g_y2[(size_t)r1 * 128 + col + 1] = acc[mt][nt][3] * s1;
                }
            }
        }
        __syncthreads();
    }
}

// ---------------- GEMM3: recon = agg3[64] @ W3 -> 128 cols + b3 ----------------
__global__ void gemm3_mma(const float* __restrict__ bias, float* __restrict__ out,
                          int N, int ntiles) {
    const int S = 72;
    extern __shared__ __nv_bfloat16 sm[];
    __nv_bfloat16* xh = sm;                 // 64*72
    __nv_bfloat16* xl = xh + 64 * S;
    __nv_bfloat16* wh = xl + 64 * S;        // 128*72
    __nv_bfloat16* wl = wh + 128 * S;
    int tid = threadIdx.x;

    {
        const unsigned* sh = (const unsigned*)g_w3t_hi;
        const unsigned* sl = (const unsigned*)g_w3t_lo;
        unsigned* dh = (unsigned*)wh;
        unsigned* dl = (unsigned*)wl;
        for (int j = tid; j < 128 * 32; j += 256) {
            int r = j >> 5, c2 = j & 31;
            dh[r * 36 + c2] = sh[j];
            dl[r * 36 + c2] = sl[j];
        }
    }

    int wid = tid >> 5, lane = tid & 31;
    int g = lane >> 2, t2 = (lane & 3) * 2;
    int wr = wid & 1, wc = wid >> 1;

    float4 pf[4];
    int tile = blockIdx.x;
    if (tile < ntiles) {
        int row0 = tile * 64;
        #pragma unroll
        for (int j = 0; j < 4; ++j) {
            int i = tid + j * 256;
            int r = i >> 4, c4 = i & 15;
            int n = row0 + r;
            pf[j] = (n < N) ? __ldg((const float4*)g_agg3 + (size_t)n * 16 + c4)
                            : make_float4(0.f, 0.f, 0.f, 0.f);
        }
    }

    for (; tile < ntiles; tile += gridDim.x) {
        int row0 = tile * 64;
        #pragma unroll
        for (int j = 0; j < 4; ++j) {
            int i = tid + j * 256;
            int r = i >> 4, c4 = i & 15;
            float vv[4] = {pf[j].x, pf[j].y, pf[j].z, pf[j].w};
            #pragma unroll
            for (int q = 0; q < 4; ++q)
                split2(vv[q], xh[r * S + c4 * 4 + q], xl[r * S + c4 * 4 + q]);
        }
        __syncthreads();

        int tnext = tile + gridDim.x;
        if (tnext < ntiles) {
            int rn0 = tnext * 64;
            #pragma unroll
            for (int j = 0; j < 4; ++j) {
                int i = tid + j * 256;
                int r = i >> 4, c4 = i & 15;
                int n = rn0 + r;
                pf[j] = (n < N) ? __ldg((const float4*)g_agg3 + (size_t)n * 16 + c4)
                                : make_float4(0.f, 0.f, 0.f, 0.f);
            }
        }

        float acc[2][4][4];
        #pragma unroll
        for (int a = 0; a < 2; ++a)
            #pragma unroll
            for (int b = 0; b < 4; ++b)
                #pragma unroll
                for (int c = 0; c < 4; ++c) acc[a][b][c] = 0.f;

        #pragma unroll
        for (int k0 = 0; k0 < 64; k0 += 16) {
            unsigned ah[2][4], al[2][4];
            #pragma unroll
            for (int mt = 0; mt < 2; ++mt) {
                int rb = wr * 32 + mt * 16 + g;
                LOAD_A(ah[mt], xh, rb, k0 + t2, S);
                LOAD_A(al[mt], xl, rb, k0 + t2, S);
            }
            #pragma unroll
            for (int nt = 0; nt < 4; ++nt) {
                int bo = (wc * 32 + nt * 8 + g) * S + k0 + t2;
                unsigned bh0 = *(const unsigned*)(wh + bo);
                unsigned bh1 = *(const unsigned*)(wh + bo + 8);
                unsigned bl0 = *(const unsigned*)(wl + bo);
                unsigned bl1 = *(const unsigned*)(wl + bo + 8);
                #pragma unroll
                for (int mt = 0; mt < 2; ++mt) {
                    mma_bf16(acc[mt][nt], ah[mt], bh0, bh1);
                    mma_bf16(acc[mt][nt], ah[mt], bl0, bl1);
                    mma_bf16(acc[mt][nt], al[mt], bh0, bh1);
                }
            }
        }

        #pragma unroll
        for (int nt = 0; nt < 4; ++nt) {
            int col = wc * 32 + nt * 8 + t2;
            float b0 = __ldg(bias + col), b1v = __ldg(bias + col + 1);
            #pragma unroll
            for (int mt = 0; mt < 2; ++mt) {
                int r0 = row0 + wr * 32 + mt * 16 + g;
                if (r0 < N) {
                    out[(size_t)r0 * 128 + col]     = acc[mt][nt][0] + b0;
                    out[(size_t)r0 * 128 + col + 1] = acc[mt][nt][1] + b1v;
                }
                int r1 = r0 + 8;
                if (r1 < N) {
                    out[(size_t)r1 * 128 + col]     = acc[mt][nt][2] + b0;
                    out[(size_t)r1 * 128 + col + 1] = acc[mt][nt][3] + b1v;
                }
            }
        }
        __syncthreads();
    }
}

// ---------------- launch ----------------
extern "C" void kernel_launch(void* const* d_in, const int* in_sizes, int n_in,
                              void* d_out, int out_size) {
    const float* features = (const float*)d_in[0];
    const int*   src      = (const int*)  d_in[1];
    const int*   dst      = (const int*)  d_in[2];
    const float* eps      = (const float*)d_in[3];
    const float* W1       = (const float*)d_in[4];
    const float* b1       = (const float*)d_in[5];
    const float* W2       = (const float*)d_in[6];
    const float* b2       = (const float*)d_in[7];
    const float* W3       = (const float*)d_in[8];
    const float* b3       = (const float*)d_in[9];

    int N = in_sizes[0] / 128;
    int E = in_sizes[1];

    float* out   = (float*)d_out;
    float* recon = out;
    float* mean  = out + (size_t)N * 128;
    float* logv  = mean + (size_t)N * 64;

    const int SMEM_G1 = (64 * 136 * 2 + 256 * 136 * 2) * 2;   // ~170KB
    const int SMEM_G2 = (64 * 264 * 2 + 128 * 264 * 2) * 2;   // ~198KB
    const int SMEM_G3 = (64 * 72 * 2 + 128 * 72 * 2) * 2;     // ~54KB
    cudaFuncSetAttribute(gemm1_mma, cudaFuncAttributeMaxDynamicSharedMemorySize, SMEM_G1);
    cudaFuncSetAttribute(gemm2_mma, cudaFuncAttributeMaxDynamicSharedMemorySize, SMEM_G2);
    cudaFuncSetAttribute(gemm3_mma, cudaFuncAttributeMaxDynamicSharedMemorySize, SMEM_G3);

    int ntiles = (N + 63) / 64;
    int nb = (N + SCAN_B - 1) / SCAN_B;
    const int GRID_P = 152;            // 1 CTA/SM persistent (gemm1/2)
    const int GRID_P3 = 152 * 4;       // 4 CTA/SM (gemm3, 54KB smem)

    split_weights<<<(256 * 128 + 255) / 256, 256>>>(W1, W2, W3);

    zero_small<<<(N + 255) / 256, 256>>>(N);
    hist_kernel<<<(E / 4 + 255) / 256, 256>>>(src, dst, E);
    scan_part<<<nb, SCAN_B>>>(N);
    scan_tops<<<1, 32>>>(nb);
    scan_add<<<(N + 255) / 256, 256>>>(N, E);
    fill_kernel<<<(E + 255) / 256, 256>>>(src, dst, E);

    gather_d128_l1<<<(N * 32 + 255) / 256, 256>>>(features, N);
    gemm1_mma<<<GRID_P, 256, SMEM_G1>>>(b1, N, ntiles);

    gemm2_mma<<<GRID_P, 256, SMEM_G2>>>(N, ntiles);
    gather_d128_l2_vae<<<(N * 32 + 255) / 256, 256>>>(b2, eps, mean, logv, N);

    gather_d64_l3<<<(N * 16 + 255) / 256, 256>>>(N);
    gemm3_mma<<<GRID_P3, 256, SMEM_G3>>>(b3, recon, N, ntiles);
}